// round 1
// baseline (speedup 1.0000x reference)
#include <cuda_runtime.h>
#include <cuda_bf16.h>

#define VOCAB 256
#define CHARS 20
#define ROWS_PER_BLOCK 8
#define THREADS 256
// floats of hist per block = 8*256 = 2048 -> 512 float4 -> 2 per thread
#define VEC_ITERS ((ROWS_PER_BLOCK * VOCAB / 4) / THREADS)

__global__ void __launch_bounds__(THREADS) fofe_hist_kernel(
    const int* __restrict__ char_ids,
    const float* __restrict__ forgetting_factor,
    float* __restrict__ out)
{
    __shared__ float hist[ROWS_PER_BLOCK * VOCAB];
    __shared__ float pw_s[CHARS];

    const int t = threadIdx.x;
    const int row0 = blockIdx.x * ROWS_PER_BLOCK;

    // Phase 1: zero the per-row histograms (vectorized, conflict-free)
    float4* h4 = reinterpret_cast<float4*>(hist);
#pragma unroll
    for (int i = 0; i < VEC_ITERS; ++i)
        h4[t + i * THREADS] = make_float4(0.f, 0.f, 0.f, 0.f);

    // Phase 1b: powers alpha^(CHARS-1-k) for k = 0..CHARS-1
    if (t < CHARS) {
        const float alpha = __ldg(forgetting_factor);
        float p = 1.f;
        const int e = (CHARS - 1) - t;
        for (int i = 0; i < e; ++i) p *= alpha;
        pw_s[t] = p;
    }
    __syncthreads();

    // Phase 2: scatter. 8 rows * 20 chars = 160 tasks; threads 0..159.
    if (t < ROWS_PER_BLOCK * CHARS) {
        const int r = t / CHARS;          // local row 0..7
        const int k = t - r * CHARS;      // char position 0..19
        const int id = __ldg(char_ids + (size_t)(row0 + r) * CHARS + k);
        atomicAdd(&hist[r * VOCAB + id], pw_s[k]);
    }
    __syncthreads();

    // Phase 3: coalesced streaming write-out (contiguous 8 KB per block)
    float4* o4 = reinterpret_cast<float4*>(out + (size_t)row0 * VOCAB);
#pragma unroll
    for (int i = 0; i < VEC_ITERS; ++i)
        o4[t + i * THREADS] = h4[t + i * THREADS];
}

extern "C" void kernel_launch(void* const* d_in, const int* in_sizes, int n_in,
                              void* d_out, int out_size) {
    // Identify inputs by size: char_ids has 256*512*20 = 2621440 elems,
    // forgetting_factor has 1.
    const int* char_ids;
    const float* ff;
    if (in_sizes[0] > in_sizes[1]) {
        char_ids = (const int*)d_in[0];
        ff = (const float*)d_in[1];
    } else {
        char_ids = (const int*)d_in[1];
        ff = (const float*)d_in[0];
    }
    float* out = (float*)d_out;

    const int n_rows = out_size / VOCAB;                 // 131072
    const int n_blocks = n_rows / ROWS_PER_BLOCK;        // 16384

    fofe_hist_kernel<<<n_blocks, THREADS>>>(char_ids, ff, out);
}